// round 13
// baseline (speedup 1.0000x reference)
#include <cuda_runtime.h>

// ProportionalNeuron LIF scan — producer/consumer + L2-prefetch pipeline.
//   ff  = x[t,b,f] * W[f,f]   (W == 0.4*I exactly -> matmul is bit-exact elementwise)
//   i   = leak_i * i + ff
//   v   = (z ? 0 : leak_v*v) + i
//   z   = v > thresh
//
// R12 -> R13: compose the two validated mechanisms. R8's producer/consumer
// split gives the best consumer (79.3us) but its one outstanding 4KB group
// can't cover DRAM latency (76.8% DRAM). R12 proved prefetch.global.L2
// (CCTL.PF2, fire-and-forget, unbounded depth) pulls DRAM->L2 effectively.
// Here the producer warp ALSO issues a lane-parallel L2 prefetch 8 slots
// (256 steps) ahead -- one instruction covers a whole 4KB slot -- so its
// cp.async fetches hit L2 (~280 cyc), for which a single outstanding group
// is 2.5x sufficient. Consumer and arithmetic identical to R8.

#define T_STEPS 2048
#define B_DIM   64
#define F_DIM   512
#define N_NEUR  (B_DIM * F_DIM)     // 32768 -> 131072 B per time step
#define GRP     32                  // steps per ring slot
#define NSLOT   4                   // ring slots (producer runs 2 ahead)
#define NITER   (T_STEPS / GRP)     // 64
#define PDSLOT  8                   // prefetch lead in slots (256 steps)

__global__ __launch_bounds__(64, 16)
void snn_scan_kernel(const float* __restrict__ x,
                     const float* __restrict__ W,
                     const float* __restrict__ leak_i,
                     const float* __restrict__ leak_v,
                     const float* __restrict__ thresh,
                     float* __restrict__ out)
{
    __shared__ float buf[NSLOT * GRP * 32];   // 16 KB: [slot][step][lane]

    const int tid  = threadIdx.x;
    const int wid  = tid >> 5;                // 0 = consumer, 1 = producer
    const int lane = tid & 31;
    const int nbase = blockIdx.x * 32;        // first neuron of this block
    const unsigned sb = (unsigned)__cvta_generic_to_shared(buf);

    if (wid == 1) {
        // ---------------- producer warp ----------------
        const float* xb = x + nbase;

        // Prefetch prologue: slots 0..PDSLOT-1 (each lane prefetches one
        // step-row = one 128B line; 32 lanes cover a whole slot).
#pragma unroll
        for (int s = 0; s < PDSLOT; ++s)
            asm volatile("prefetch.global.L2 [%0];"
                         :: "l"(xb + (s * GRP + lane) * N_NEUR));

        // cp.async prologue: slots 0 and 1 (one slot = 32 steps x 32 neurons
        // = 4 KB as 256 x 16B ops: idx = j*32+lane, k = idx>>3, q = idx&7).
#pragma unroll
        for (int s = 0; s < 2; ++s) {
            const unsigned sbase = sb + s * (GRP * 128);
#pragma unroll
            for (int j = 0; j < 8; ++j) {
                const int idx = j * 32 + lane;
                const int k = idx >> 3, q = idx & 7;
                asm volatile("cp.async.cg.shared.global [%0], [%1], 16;\n"
                             :: "r"(sbase + (unsigned)(k * 128 + q * 16)),
                                "l"(xb + (s * GRP + k) * N_NEUR + q * 4));
            }
            asm volatile("cp.async.commit_group;\n" ::: "memory");
        }
        asm volatile("cp.async.wait_group 1;\n" ::: "memory");  // slot 0 ready
        __syncthreads();

        for (int it = 0; it < NITER; ++it) {
            // L2 prefetch PDSLOT slots ahead (lane-parallel, 1 instr/slot)
            const int tpf = (it + PDSLOT) * GRP;
            if (tpf < T_STEPS)
                asm volatile("prefetch.global.L2 [%0];"
                             :: "l"(xb + (tpf + lane) * N_NEUR));

            const int tload = (it + 2) * GRP;           // steps for slot (it+2)%4
            if (tload < T_STEPS) {
                const unsigned sbase = sb + ((it + 2) & (NSLOT - 1)) * (GRP * 128);
                const float* gp = xb + tload * N_NEUR;
#pragma unroll
                for (int j = 0; j < 8; ++j) {
                    const int idx = j * 32 + lane;
                    const int k = idx >> 3, q = idx & 7;
                    asm volatile("cp.async.cg.shared.global [%0], [%1], 16;\n"
                                 :: "r"(sbase + (unsigned)(k * 128 + q * 16)),
                                    "l"(gp + k * N_NEUR + q * 4));
                }
            }
            // Always commit (possibly empty) so wait_group accounting is uniform.
            asm volatile("cp.async.commit_group;\n" ::: "memory");
            asm volatile("cp.async.wait_group 1;\n" ::: "memory"); // slot it+1 ready
            __syncthreads();
        }
    } else {
        // ---------------- consumer warp ----------------
        const int n = nbase + lane;
        const int f = n & (F_DIM - 1);

        const float wff = W[f * F_DIM + f];  // diagonal; off-diag terms exactly 0
        const float li  = leak_i[f];
        const float lv  = leak_v[f];
        const float th  = thresh[f];

        float i_s = 0.0f;
        float v_s = 0.0f;
        bool  zb  = false;

        __syncthreads();   // matches producer prologue barrier; slot 0 ready

        for (int it = 0; it < NITER; ++it) {
            const float* sp = buf + (it & (NSLOT - 1)) * (GRP * 32) + lane;
            float* op = out + it * GRP * N_NEUR + n;

#pragma unroll
            for (int k = 0; k < GRP; ++k) {
                const float xv  = sp[k * 32];
                const float ff  = __fmul_rn(xv, wff);
                i_s = __fadd_rn(__fmul_rn(li, i_s), ff);
                const float lvv = __fmul_rn(lv, v_s);
                v_s = __fadd_rn(zb ? 0.0f : lvv, i_s);
                zb  = (v_s > th);
                __stcs(op + k * N_NEUR, zb ? 1.0f : 0.0f);
            }
            __syncthreads();   // release slot `it` for producer reuse
        }
    }
}

extern "C" void kernel_launch(void* const* d_in, const int* in_sizes, int n_in,
                              void* d_out, int out_size)
{
    const float* x      = (const float*)d_in[0];
    const float* W      = (const float*)d_in[1];
    const float* leak_i = (const float*)d_in[2];
    const float* leak_v = (const float*)d_in[3];
    const float* thresh = (const float*)d_in[4];
    float* out = (float*)d_out;

    const int block = 64;               // warp0 consumer, warp1 producer
    const int grid  = N_NEUR / 32;      // 1024 blocks
    snn_scan_kernel<<<grid, block>>>(x, W, leak_i, leak_v, thresh, out);
}

// round 14
// speedup vs baseline: 1.1762x; 1.1762x over previous
#include <cuda_runtime.h>
#include <cstdint>

// ProportionalNeuron LIF scan — R8 producer/consumer, mbarrier-decoupled.
//   ff  = x[t,b,f] * W[f,f]   (W == 0.4*I exactly -> matmul is bit-exact elementwise)
//   i   = leak_i * i + ff
//   v   = (z ? 0 : leak_v*v) + i
//   z   = v > thresh
//
// R13 -> R14: keep R8's proven depth (one pending 4KB cp.async group,
// wait_group 1) but replace the __syncthreads lock-step with per-slot
// full/empty mbarriers. full[s] is signaled by cp.async.mbarrier.arrive.noinc
// (32 producer lanes, on copy COMPLETION); empty[s] by consumer lane 0 after
// use. Producer issue bursts and waits now overlap consumer compute instead
// of adding to it serially. Everything else identical to R8; arithmetic
// bit-identical (rel_err unchanged).

#define T_STEPS 2048
#define B_DIM   64
#define F_DIM   512
#define N_NEUR  (B_DIM * F_DIM)     // 32768 -> 131072 B per time step
#define GRP     32                  // steps per ring slot (4 KB)
#define NSLOT   4                   // ring slots
#define NITER   (T_STEPS / GRP)     // 64

// ---- mbarrier helpers (cta scope) ----
__device__ __forceinline__ void mbar_init(uint32_t a, uint32_t cnt) {
    asm volatile("mbarrier.init.shared.b64 [%0], %1;" :: "r"(a), "r"(cnt) : "memory");
}
__device__ __forceinline__ void mbar_arrive(uint32_t a) {
    asm volatile("mbarrier.arrive.shared.b64 _, [%0];" :: "r"(a) : "memory");
}
__device__ __forceinline__ void mbar_wait_acq(uint32_t a, uint32_t parity) {
    asm volatile(
        "{\n\t.reg .pred P;\n\t"
        "W_%=:\n\t"
        "mbarrier.try_wait.parity.acquire.cta.shared::cta.b64 P, [%0], %1, 0x989680;\n\t"
        "@P bra D_%=;\n\t"
        "bra W_%=;\n\t"
        "D_%=:\n\t}"
        :: "r"(a), "r"(parity) : "memory");
}
__device__ __forceinline__ void mbar_wait_rlx(uint32_t a, uint32_t parity) {
    asm volatile(
        "{\n\t.reg .pred P;\n\t"
        "W_%=:\n\t"
        "mbarrier.try_wait.parity.relaxed.cta.shared::cta.b64 P, [%0], %1, 0x989680;\n\t"
        "@P bra D_%=;\n\t"
        "bra W_%=;\n\t"
        "D_%=:\n\t}"
        :: "r"(a), "r"(parity) : "memory");
}

__global__ __launch_bounds__(64, 16)
void snn_scan_kernel(const float* __restrict__ x,
                     const float* __restrict__ W,
                     const float* __restrict__ leak_i,
                     const float* __restrict__ leak_v,
                     const float* __restrict__ thresh,
                     float* __restrict__ out)
{
    __shared__ float buf[NSLOT * GRP * 32];      // 16 KB: [slot][step][lane]
    __shared__ __align__(8) uint64_t mbar[2 * NSLOT];  // full[s]@s*16, empty[s]@s*16+8

    const int tid  = threadIdx.x;
    const int wid  = tid >> 5;                   // 0 = consumer, 1 = producer
    const int lane = tid & 31;
    const int nbase = blockIdx.x * 32;           // first neuron of this block
    const unsigned sb = (unsigned)__cvta_generic_to_shared(buf);
    const uint32_t mb = (uint32_t)__cvta_generic_to_shared(mbar);

    if (tid == 0) {
#pragma unroll
        for (int s = 0; s < NSLOT; ++s) {
            mbar_init(mb + s * 16, 32);          // full: 32 producer-lane arrivals
            mbar_init(mb + s * 16 + 8, 1);       // empty: consumer lane0 arrival
        }
    }
    __syncthreads();

    if (wid == 1) {
        // ---------------- producer warp ----------------
        // Slot = 32 steps x 32 neurons = 4 KB, as 256 x 16B cp.async ops
        // (idx = j*32+lane, k = idx>>3 step, q = idx&7 quad).
        const float* xb = x + nbase;

        for (int it = 0; it < NITER; ++it) {
            const int slot = it & (NSLOT - 1);
            const uint32_t eph = (((uint32_t)it >> 2) & 1u) ^ 1u;
            mbar_wait_rlx(mb + slot * 16 + 8, eph);      // slot empty
                                                         // (first 4 pass immediately)
            const unsigned sbase = sb + slot * (GRP * 128);
            const float* gp = xb + it * GRP * N_NEUR;
#pragma unroll
            for (int j = 0; j < 8; ++j) {
                const int idx = j * 32 + lane;
                const int k = idx >> 3, q = idx & 7;
                asm volatile("cp.async.cg.shared.global [%0], [%1], 16;\n"
                             :: "r"(sbase + (unsigned)(k * 128 + q * 16)),
                                "l"(gp + k * N_NEUR + q * 4));
            }
            // Arrive on full[slot] when this lane's copies complete.
            asm volatile("cp.async.mbarrier.arrive.noinc.shared.b64 [%0];"
                         :: "r"(mb + slot * 16) : "memory");
            // Pacing: keep at most one group pending (R8's proven L1tex depth).
            asm volatile("cp.async.commit_group;\n" ::: "memory");
            asm volatile("cp.async.wait_group 1;\n" ::: "memory");
        }
    } else {
        // ---------------- consumer warp ----------------
        const int n = nbase + lane;
        const int f = n & (F_DIM - 1);

        const float wff = W[f * F_DIM + f];  // diagonal; off-diag terms exactly 0
        const float li  = leak_i[f];
        const float lv  = leak_v[f];
        const float th  = thresh[f];

        float i_s = 0.0f;
        float v_s = 0.0f;
        bool  zb  = false;

        for (int it = 0; it < NITER; ++it) {
            const int slot = it & (NSLOT - 1);
            const uint32_t fph = ((uint32_t)it >> 2) & 1u;
            mbar_wait_acq(mb + slot * 16, fph);          // slot full

            const float* sp = buf + slot * (GRP * 32) + lane;
            float* op = out + it * GRP * N_NEUR + n;
#pragma unroll
            for (int k = 0; k < GRP; ++k) {
                const float xv  = sp[k * 32];
                const float ff  = __fmul_rn(xv, wff);
                i_s = __fadd_rn(__fmul_rn(li, i_s), ff);
                const float lvv = __fmul_rn(lv, v_s);
                v_s = __fadd_rn(zb ? 0.0f : lvv, i_s);
                zb  = (v_s > th);
                __stcs(op + k * N_NEUR, zb ? 1.0f : 0.0f);
            }

            __syncwarp();
            if (lane == 0) mbar_arrive(mb + slot * 16 + 8);   // slot empty
        }
    }
}

extern "C" void kernel_launch(void* const* d_in, const int* in_sizes, int n_in,
                              void* d_out, int out_size)
{
    const float* x      = (const float*)d_in[0];
    const float* W      = (const float*)d_in[1];
    const float* leak_i = (const float*)d_in[2];
    const float* leak_v = (const float*)d_in[3];
    const float* thresh = (const float*)d_in[4];
    float* out = (float*)d_out;

    const int block = 64;               // warp0 consumer, warp1 producer
    const int grid  = N_NEUR / 32;      // 1024 blocks
    snn_scan_kernel<<<grid, block>>>(x, W, leak_i, leak_v, thresh, out);
}

// round 15
// speedup vs baseline: 1.2323x; 1.0477x over previous
#include <cuda_runtime.h>
#include <cstdint>

// ProportionalNeuron LIF scan — 1 producer + 2 consumer warps per block.
//   ff  = x[t,b,f] * W[f,f]   (W == 0.4*I exactly -> matmul is bit-exact elementwise)
//   i   = leak_i * i + ff
//   v   = (z ? 0 : leak_v*v) + i
//   z   = v > thresh
//
// R14 -> R15: R8/R14 pin at exactly 6.1 TB/s regardless of sync/depth/pipe ->
// suspect DRAM row locality (each block touches only 128B per 128KB-strided
// row). Widen block footprint to 64 neurons: 2 consumer warps + 1 producer,
// 512 blocks. Every read slot row and store row is now 256B contiguous,
// halving distinct request streams per DRAM row and halving producer warps.
// Slot 8KB, NSLOT 4 (32KB smem, <=4 blocks/SM). mbarrier protocol as R14
// (empty count 2). Consumer body and arithmetic bit-identical.

#define T_STEPS 2048
#define B_DIM   64
#define F_DIM   512
#define N_NEUR  (B_DIM * F_DIM)     // 32768 -> 131072 B per time step
#define GRP     32                  // steps per ring slot
#define NBLK    64                  // neurons per block
#define NSLOT   4                   // ring slots (slot = 8 KB)
#define NITER   (T_STEPS / GRP)     // 64

// ---- mbarrier helpers (cta scope) ----
__device__ __forceinline__ void mbar_init(uint32_t a, uint32_t cnt) {
    asm volatile("mbarrier.init.shared.b64 [%0], %1;" :: "r"(a), "r"(cnt) : "memory");
}
__device__ __forceinline__ void mbar_arrive(uint32_t a) {
    asm volatile("mbarrier.arrive.shared.b64 _, [%0];" :: "r"(a) : "memory");
}
__device__ __forceinline__ void mbar_wait_acq(uint32_t a, uint32_t parity) {
    asm volatile(
        "{\n\t.reg .pred P;\n\t"
        "W_%=:\n\t"
        "mbarrier.try_wait.parity.acquire.cta.shared::cta.b64 P, [%0], %1, 0x989680;\n\t"
        "@P bra D_%=;\n\t"
        "bra W_%=;\n\t"
        "D_%=:\n\t}"
        :: "r"(a), "r"(parity) : "memory");
}
__device__ __forceinline__ void mbar_wait_rlx(uint32_t a, uint32_t parity) {
    asm volatile(
        "{\n\t.reg .pred P;\n\t"
        "W_%=:\n\t"
        "mbarrier.try_wait.parity.relaxed.cta.shared::cta.b64 P, [%0], %1, 0x989680;\n\t"
        "@P bra D_%=;\n\t"
        "bra W_%=;\n\t"
        "D_%=:\n\t}"
        :: "r"(a), "r"(parity) : "memory");
}

__global__ __launch_bounds__(96)
void snn_scan_kernel(const float* __restrict__ x,
                     const float* __restrict__ W,
                     const float* __restrict__ leak_i,
                     const float* __restrict__ leak_v,
                     const float* __restrict__ thresh,
                     float* __restrict__ out)
{
    __shared__ float buf[NSLOT * GRP * NBLK];          // 32 KB: [slot][step][neuron]
    __shared__ __align__(8) uint64_t mbar[2 * NSLOT];  // full[s]@s*16, empty[s]@s*16+8

    const int tid  = threadIdx.x;
    const int wid  = tid >> 5;                 // 0,1 = consumers, 2 = producer
    const int lane = tid & 31;
    const int nbase = blockIdx.x * NBLK;       // first neuron of this block
    const unsigned sb = (unsigned)__cvta_generic_to_shared(buf);
    const uint32_t mb = (uint32_t)__cvta_generic_to_shared(mbar);

    if (tid == 0) {
#pragma unroll
        for (int s = 0; s < NSLOT; ++s) {
            mbar_init(mb + s * 16, 32);        // full: 32 producer-lane completions
            mbar_init(mb + s * 16 + 8, 2);     // empty: lane0 of each consumer warp
        }
    }
    __syncthreads();

    if (wid == 2) {
        // ---------------- producer warp ----------------
        // Slot = 32 steps x 64 neurons = 8 KB, as 512 x 16B cp.async ops:
        // idx = j*32+lane (j 0..15), step k = idx>>4, quad q = idx&15.
        // Each step-row is 256 B contiguous in gmem (2 consecutive lines).
        const float* xb = x + nbase;

        for (int it = 0; it < NITER; ++it) {
            const int slot = it & (NSLOT - 1);
            const uint32_t eph = (((uint32_t)it >> 2) & 1u) ^ 1u;
            mbar_wait_rlx(mb + slot * 16 + 8, eph);      // slot empty
                                                         // (first 4 pass immediately)
            const unsigned sbase = sb + slot * (GRP * NBLK * 4);
            const float* gp = xb + it * GRP * N_NEUR;
#pragma unroll
            for (int j = 0; j < 16; ++j) {
                const int idx = j * 32 + lane;
                const int k = idx >> 4, q = idx & 15;
                asm volatile("cp.async.cg.shared.global [%0], [%1], 16;\n"
                             :: "r"(sbase + (unsigned)(k * (NBLK * 4) + q * 16)),
                                "l"(gp + k * N_NEUR + q * 4));
            }
            // Arrive on full[slot] when this lane's copies complete.
            asm volatile("cp.async.mbarrier.arrive.noinc.shared.b64 [%0];"
                         :: "r"(mb + slot * 16) : "memory");
            // Pacing: at most one group pending (proven L1tex-friendly depth).
            asm volatile("cp.async.commit_group;\n" ::: "memory");
            asm volatile("cp.async.wait_group 1;\n" ::: "memory");
        }
    } else {
        // ---------------- consumer warps (wid = 0,1) ----------------
        const int n = nbase + wid * 32 + lane;
        const int f = n & (F_DIM - 1);

        const float wff = W[f * F_DIM + f];  // diagonal; off-diag terms exactly 0
        const float li  = leak_i[f];
        const float lv  = leak_v[f];
        const float th  = thresh[f];

        float i_s = 0.0f;
        float v_s = 0.0f;
        bool  zb  = false;

        const int coff = wid * 32 + lane;    // column within the 64-neuron row

        for (int it = 0; it < NITER; ++it) {
            const int slot = it & (NSLOT - 1);
            const uint32_t fph = ((uint32_t)it >> 2) & 1u;
            mbar_wait_acq(mb + slot * 16, fph);          // slot full

            const float* sp = buf + slot * (GRP * NBLK) + coff;
            float* op = out + it * GRP * N_NEUR + n;
#pragma unroll
            for (int k = 0; k < GRP; ++k) {
                const float xv  = sp[k * NBLK];
                const float ff  = __fmul_rn(xv, wff);
                i_s = __fadd_rn(__fmul_rn(li, i_s), ff);
                const float lvv = __fmul_rn(lv, v_s);
                v_s = __fadd_rn(zb ? 0.0f : lvv, i_s);
                zb  = (v_s > th);
                __stcs(op + k * N_NEUR, zb ? 1.0f : 0.0f);
            }

            __syncwarp();
            if (lane == 0) mbar_arrive(mb + slot * 16 + 8);   // slot empty (2 arrivals)
        }
    }
}

extern "C" void kernel_launch(void* const* d_in, const int* in_sizes, int n_in,
                              void* d_out, int out_size)
{
    const float* x      = (const float*)d_in[0];
    const float* W      = (const float*)d_in[1];
    const float* leak_i = (const float*)d_in[2];
    const float* leak_v = (const float*)d_in[3];
    const float* thresh = (const float*)d_in[4];
    float* out = (float*)d_out;

    const int block = 96;               // warp0/1 consumers, warp2 producer
    const int grid  = N_NEUR / NBLK;    // 512 blocks
    snn_scan_kernel<<<grid, block>>>(x, W, leak_i, leak_v, thresh, out);
}

// round 16
// speedup vs baseline: 1.2637x; 1.0254x over previous
#include <cuda_runtime.h>
#include <cstdint>

// ProportionalNeuron LIF scan — 1 producer + 4 consumer warps per block.
//   ff  = x[t,b,f] * W[f,f]   (W == 0.4*I exactly -> matmul is bit-exact elementwise)
//   i   = leak_i * i + ff
//   v   = (z ? 0 : leak_v*v) + i
//   z   = v > thresh
//
// R15 -> R16: contiguity ladder, next rung. 128 neurons/block: every
// read-slot row and store row is 512B contiguous (4 lines), quartering the
// distinct request streams per DRAM row vs R14 and halving producer warps
// again. 256 blocks x 160 threads; slot 16KB, NSLOT 4 -> 64KB smem
// (3 blocks/SM >= 1.73 needed). Protocol and consumer body identical to R15
// (empty-mbar count 4). Arithmetic bit-identical.

#define T_STEPS 2048
#define B_DIM   64
#define F_DIM   512
#define N_NEUR  (B_DIM * F_DIM)     // 32768 -> 131072 B per time step
#define GRP     32                  // steps per ring slot
#define NBLK    128                 // neurons per block (512 B per step-row)
#define NSLOT   4                   // ring slots (slot = 16 KB)
#define NITER   (T_STEPS / GRP)     // 64

// ---- mbarrier helpers (cta scope) ----
__device__ __forceinline__ void mbar_init(uint32_t a, uint32_t cnt) {
    asm volatile("mbarrier.init.shared.b64 [%0], %1;" :: "r"(a), "r"(cnt) : "memory");
}
__device__ __forceinline__ void mbar_arrive(uint32_t a) {
    asm volatile("mbarrier.arrive.shared.b64 _, [%0];" :: "r"(a) : "memory");
}
__device__ __forceinline__ void mbar_wait_acq(uint32_t a, uint32_t parity) {
    asm volatile(
        "{\n\t.reg .pred P;\n\t"
        "W_%=:\n\t"
        "mbarrier.try_wait.parity.acquire.cta.shared::cta.b64 P, [%0], %1, 0x989680;\n\t"
        "@P bra D_%=;\n\t"
        "bra W_%=;\n\t"
        "D_%=:\n\t}"
        :: "r"(a), "r"(parity) : "memory");
}
__device__ __forceinline__ void mbar_wait_rlx(uint32_t a, uint32_t parity) {
    asm volatile(
        "{\n\t.reg .pred P;\n\t"
        "W_%=:\n\t"
        "mbarrier.try_wait.parity.relaxed.cta.shared::cta.b64 P, [%0], %1, 0x989680;\n\t"
        "@P bra D_%=;\n\t"
        "bra W_%=;\n\t"
        "D_%=:\n\t}"
        :: "r"(a), "r"(parity) : "memory");
}

__global__ __launch_bounds__(160)
void snn_scan_kernel(const float* __restrict__ x,
                     const float* __restrict__ W,
                     const float* __restrict__ leak_i,
                     const float* __restrict__ leak_v,
                     const float* __restrict__ thresh,
                     float* __restrict__ out)
{
    __shared__ float buf[NSLOT * GRP * NBLK];          // 64 KB: [slot][step][neuron]
    __shared__ __align__(8) uint64_t mbar[2 * NSLOT];  // full[s]@s*16, empty[s]@s*16+8

    const int tid  = threadIdx.x;
    const int wid  = tid >> 5;                 // 0..3 = consumers, 4 = producer
    const int lane = tid & 31;
    const int nbase = blockIdx.x * NBLK;       // first neuron of this block
    const unsigned sb = (unsigned)__cvta_generic_to_shared(buf);
    const uint32_t mb = (uint32_t)__cvta_generic_to_shared(mbar);

    if (tid == 0) {
#pragma unroll
        for (int s = 0; s < NSLOT; ++s) {
            mbar_init(mb + s * 16, 32);        // full: 32 producer-lane completions
            mbar_init(mb + s * 16 + 8, 4);     // empty: lane0 of each consumer warp
        }
    }
    __syncthreads();

    if (wid == 4) {
        // ---------------- producer warp ----------------
        // Slot = 32 steps x 128 neurons = 16 KB, as 1024 x 16B cp.async ops:
        // idx = j*32+lane (j 0..31), step k = idx>>5, quad q = idx&31.
        // Each step-row is 512 B contiguous in gmem (4 consecutive lines).
        const float* xb = x + nbase;

        for (int it = 0; it < NITER; ++it) {
            const int slot = it & (NSLOT - 1);
            const uint32_t eph = (((uint32_t)it >> 2) & 1u) ^ 1u;
            mbar_wait_rlx(mb + slot * 16 + 8, eph);      // slot empty
                                                         // (first 4 pass immediately)
            const unsigned sbase = sb + slot * (GRP * NBLK * 4);
            const float* gp = xb + it * GRP * N_NEUR;
#pragma unroll
            for (int j = 0; j < 32; ++j) {
                const int idx = j * 32 + lane;
                const int k = idx >> 5, q = idx & 31;
                asm volatile("cp.async.cg.shared.global [%0], [%1], 16;\n"
                             :: "r"(sbase + (unsigned)(k * (NBLK * 4) + q * 16)),
                                "l"(gp + k * N_NEUR + q * 4));
            }
            // Arrive on full[slot] when this lane's copies complete.
            asm volatile("cp.async.mbarrier.arrive.noinc.shared.b64 [%0];"
                         :: "r"(mb + slot * 16) : "memory");
            // Pacing: at most one group pending (proven L1tex-friendly depth).
            asm volatile("cp.async.commit_group;\n" ::: "memory");
            asm volatile("cp.async.wait_group 1;\n" ::: "memory");
        }
    } else {
        // ---------------- consumer warps (wid = 0..3) ----------------
        const int coff = wid * 32 + lane;    // column within the 128-neuron row
        const int n = nbase + coff;
        const int f = n & (F_DIM - 1);

        const float wff = W[f * F_DIM + f];  // diagonal; off-diag terms exactly 0
        const float li  = leak_i[f];
        const float lv  = leak_v[f];
        const float th  = thresh[f];

        float i_s = 0.0f;
        float v_s = 0.0f;
        bool  zb  = false;

        for (int it = 0; it < NITER; ++it) {
            const int slot = it & (NSLOT - 1);
            const uint32_t fph = ((uint32_t)it >> 2) & 1u;
            mbar_wait_acq(mb + slot * 16, fph);          // slot full

            const float* sp = buf + slot * (GRP * NBLK) + coff;
            float* op = out + it * GRP * N_NEUR + n;
#pragma unroll
            for (int k = 0; k < GRP; ++k) {
                const float xv  = sp[k * NBLK];
                const float ff  = __fmul_rn(xv, wff);
                i_s = __fadd_rn(__fmul_rn(li, i_s), ff);
                const float lvv = __fmul_rn(lv, v_s);
                v_s = __fadd_rn(zb ? 0.0f : lvv, i_s);
                zb  = (v_s > th);
                __stcs(op + k * N_NEUR, zb ? 1.0f : 0.0f);
            }

            __syncwarp();
            if (lane == 0) mbar_arrive(mb + slot * 16 + 8);   // slot empty (4 arrivals)
        }
    }
}

extern "C" void kernel_launch(void* const* d_in, const int* in_sizes, int n_in,
                              void* d_out, int out_size)
{
    const float* x      = (const float*)d_in[0];
    const float* W      = (const float*)d_in[1];
    const float* leak_i = (const float*)d_in[2];
    const float* leak_v = (const float*)d_in[3];
    const float* thresh = (const float*)d_in[4];
    float* out = (float*)d_out;

    const int block = 160;              // warp0-3 consumers, warp4 producer
    const int grid  = N_NEUR / NBLK;    // 256 blocks
    snn_scan_kernel<<<grid, block>>>(x, W, leak_i, leak_v, thresh, out);
}